// round 7
// baseline (speedup 1.0000x reference)
#include <cuda_runtime.h>
#include <cstdint>

// Problem constants (fixed-shape instance)
#define BB 16
#define CC 192
#define HH 224
#define WW 224
#define SS 196

#define ROWCHUNKS 16
#define ROWS_PER (HH / ROWCHUNKS)     // 14
#define PIX (ROWS_PER * WW)           // 3136
#define PLANE_BYTES (PIX * 4)         // 12544 (contiguous per channel per chunk)

#define NC 4                          // channels per group
#define NGROUPS (CC / NC)             // 48
#define NSTAGE 2                      // pipeline depth
#define STRIDE 3144                   // padded plane stride (floats); %32==8
#define GROUP_BYTES (NC * PLANE_BYTES) // 50176
#define NTH 512

// dyn smem: ring[NSTAGE*NC*STRIDE] f32 | sorted[PIX] u16 | hist[SS] i32 | mbars
// sort scratch (segtmp PIX i32 + scanbuf NTH i32) overlaid into ring.
#define RING_FLOATS (NSTAGE * NC * STRIDE)          // 25152 -> 100608 B
#define SMEM_BYTES (RING_FLOATS * 4 + PIX * 2 + SS * 4 + 64)   // ~107.7 KB -> 2 CTAs/SM

__device__ float g_counts[BB * SS];

__device__ __forceinline__ uint32_t smem_u32(const void* p) {
    uint32_t a;
    asm("{ .reg .u64 t; cvta.to.shared.u64 t, %1; cvt.u32.u64 %0, t; }" : "=r"(a) : "l"(p));
    return a;
}
__device__ __forceinline__ void mbar_init(uint32_t mbar, uint32_t cnt) {
    asm volatile("mbarrier.init.shared.b64 [%0], %1;" :: "r"(mbar), "r"(cnt) : "memory");
}
__device__ __forceinline__ void mbar_expect_tx(uint32_t mbar, uint32_t bytes) {
    asm volatile("mbarrier.arrive.expect_tx.shared.b64 _, [%0], %1;" :: "r"(mbar), "r"(bytes) : "memory");
}
__device__ __forceinline__ void mbar_wait(uint32_t mbar, uint32_t parity) {
    asm volatile(
        "{\n\t"
        ".reg .pred P;\n\t"
        "W_%=:\n\t"
        "mbarrier.try_wait.parity.acquire.cta.shared::cta.b64 P, [%0], %1, 0x989680;\n\t"
        "@P bra D_%=;\n\t"
        "bra W_%=;\n\t"
        "D_%=:\n\t"
        "}" :: "r"(mbar), "r"(parity) : "memory");
}
__device__ __forceinline__ void bulk_g2s(uint32_t dst, const void* src, uint32_t bytes, uint32_t mbar) {
    asm volatile("cp.async.bulk.shared::cta.global.mbarrier::complete_tx::bytes [%0], [%1], %2, [%3];"
                 :: "r"(dst), "l"(src), "r"(bytes), "r"(mbar) : "memory");
}
__device__ __forceinline__ void red_add_v4(float* addr, float a, float b, float c, float d) {
    asm volatile("red.global.add.v4.f32 [%0], {%1,%2,%3,%4};"
                 :: "l"(addr), "f"(a), "f"(b), "f"(c), "f"(d) : "memory");
}

// ---------------- Kernel 1: zero sums (d_out) and counts ----------------
__global__ void zero_kernel(float* __restrict__ out) {
    const int n = BB * SS * CC;
    int idx = blockIdx.x * blockDim.x + threadIdx.x;
    int stride = gridDim.x * blockDim.x;
    for (int i = idx; i < n; i += stride) out[i] = 0.0f;
    for (int i = idx; i < BB * SS; i += stride) g_counts[i] = 0.0f;
}

// ---------------- Kernel 2: sort once + pipelined run-loop segmented reduction ----------------
// grid: (ROWCHUNKS, 1, BB) = 256 CTAs, block: 512, 2 CTAs/SM -> single wave
__global__ __launch_bounds__(NTH, 2) void accum_kernel(
    const float* __restrict__ feat,   // (B, C, H, W) fp32
    const int* __restrict__ seg,      // (B, H, W) int32
    float* __restrict__ out)          // (B, S, C) fp32 (sums)
{
    extern __shared__ char smem_raw[];
    float* ring = (float*)smem_raw;                             // NSTAGE*NC*STRIDE f32
    unsigned short* sorted = (unsigned short*)(ring + RING_FLOATS);  // PIX u16
    int* hist = (int*)(sorted + PIX);                           // SS (post-scatter: END offsets)
    unsigned long long* mbars = (unsigned long long*)(hist + SS);    // NSTAGE

    // sort scratch overlaid into ring (dead before TMA starts)
    int* segtmp  = (int*)ring;        // PIX ints
    int* scanbuf = segtmp + PIX;      // NTH ints

    const int tid = threadIdx.x;
    const int b   = blockIdx.z;
    const int h0  = blockIdx.x * ROWS_PER;

    const uint32_t mbar0 = smem_u32(mbars);

    if (tid == 0) {
        #pragma unroll
        for (int s = 0; s < NSTAGE; ++s) mbar_init(mbar0 + 8 * s, 1);
    }

    // ================= Phase 1: counting sort by segment id =================
    for (int i = tid; i < SS; i += NTH) hist[i] = 0;
    __syncthreads();

    const int* segbase = seg + ((size_t)b * HH + h0) * WW;   // contiguous PIX ints
    for (int i = tid; i < PIX; i += NTH) {
        int s = segbase[i];
        s = min(max(s, 0), SS - 1);
        segtmp[i] = s;
        atomicAdd(&hist[s], 1);
    }
    __syncthreads();

    // counts (each CTA owns a unique (b, rowchunk))
    for (int i = tid; i < SS; i += NTH)
        atomicAdd(&g_counts[b * SS + i], (float)hist[i]);

    // block-wide exclusive scan of hist (SS <= NTH)
    int v = (tid < SS) ? hist[tid] : 0;
    scanbuf[tid] = v;
    __syncthreads();
    #pragma unroll
    for (int d = 1; d < NTH; d <<= 1) {
        int t = (tid >= d) ? scanbuf[tid - d] : 0;
        __syncthreads();
        scanbuf[tid] += t;
        __syncthreads();
    }
    if (tid < SS) hist[tid] = scanbuf[tid] - v;  // exclusive start offsets
    __syncthreads();

    // scatter; afterwards hist[s] = END offset of segment s
    for (int i = tid; i < PIX; i += NTH) {
        int s = segtmp[i];
        int pos = atomicAdd(&hist[s], 1);
        sorted[pos] = (unsigned short)i;
    }
    __syncthreads();   // sort done; ring scratch dead -> safe for TMA

    // ================= Phase 2: pipelined channel groups =================
    const float* featbase = feat + ((size_t)b * CC * HH + h0) * WW;  // + c*HH*WW
    const size_t plane = (size_t)HH * WW;
    const uint32_t ring_s = smem_u32(ring);

    // prologue: issue TMAs for groups 0..NSTAGE-1
    if (tid == 0) {
        #pragma unroll
        for (int s = 0; s < NSTAGE; ++s) {
            mbar_expect_tx(mbar0 + 8 * s, GROUP_BYTES);
            #pragma unroll
            for (int c = 0; c < NC; ++c) {
                bulk_g2s(ring_s + (uint32_t)((s * NC + c) * STRIDE) * 4,
                         featbase + (size_t)(s * NC + c) * plane,
                         PLANE_BYTES, mbar0 + 8 * s);
            }
        }
    }

    // balanced windows: exact partition, PIX/NTH = 6.125 = 49/8
    const int start = (tid * 49) >> 3;
    const int end   = ((tid + 1) * 49) >> 3;

    // first segment of this window: smallest s with hist[s] > start (binary search, once)
    int seg0;
    {
        int lo = 0, hi = SS - 1;
        while (lo < hi) {
            int mid = (lo + hi) >> 1;
            if (hist[mid] > start) hi = mid; else lo = mid + 1;
        }
        seg0 = lo;
    }

    float* obase0 = out + (size_t)b * SS * CC;

    for (int g = 0; g < NGROUPS; ++g) {
        const int st = g & 1;
        const uint32_t mb = mbar0 + 8 * st;
        mbar_wait(mb, (g >> 1) & 1);

        const float* p0 = ring + (st * NC + 0) * STRIDE;
        const float* p1 = ring + (st * NC + 1) * STRIDE;
        const float* p2 = ring + (st * NC + 2) * STRIDE;
        const float* p3 = ring + (st * NC + 3) * STRIDE;
        float* obase = obase0 + g * NC;

        int i = start;
        int s = seg0;
        while (i < end) {
            int rend = hist[s];
            if (rend > end) rend = end;
            float a0 = 0.f, a1 = 0.f, a2 = 0.f, a3 = 0.f;
            #pragma unroll 4
            for (; i < rend; ++i) {
                int idx = sorted[i];
                a0 += p0[idx];
                a1 += p1[idx];
                a2 += p2[idx];
                a3 += p3[idx];
            }
            red_add_v4(obase + (size_t)s * CC, a0, a1, a2, a3);
            if (i < end) {
                do { ++s; } while (hist[s] <= i);
            }
        }

        __syncthreads();   // all gathers on buffer st complete before refill

        if (tid == 0 && g + NSTAGE < NGROUPS) {
            const int gn = g + NSTAGE;
            mbar_expect_tx(mb, GROUP_BYTES);
            #pragma unroll
            for (int c = 0; c < NC; ++c) {
                bulk_g2s(ring_s + (uint32_t)((st * NC + c) * STRIDE) * 4,
                         featbase + (size_t)(gn * NC + c) * plane,
                         PLANE_BYTES, mb);
            }
        }
    }
}

// ---------------- Kernel 3: finalize (divide by count, add positional embedding) ----------------
__global__ void finalize_kernel(
    float* __restrict__ out,                   // (B, S, C) sums -> final
    const float* __restrict__ centroid,        // (B, S, 2)
    const float* __restrict__ posW,            // (2, C)
    const float* __restrict__ posb)            // (C,)
{
    int idx = blockIdx.x * blockDim.x + threadIdx.x;
    if (idx >= BB * SS * CC) return;
    int c  = idx % CC;
    int bs = idx / CC;
    float cnt = g_counts[bs];
    float cx = centroid[bs * 2 + 0] * (1.0f / WW);
    float cy = centroid[bs * 2 + 1] * (1.0f / HH);
    float pos = fmaf(cx, posW[c], fmaf(cy, posW[CC + c], posb[c]));
    out[idx] = out[idx] / fmaxf(cnt, 1.0f) + pos;
}

extern "C" void kernel_launch(void* const* d_in, const int* in_sizes, int n_in,
                              void* d_out, int out_size)
{
    // inputs: 0=img(unused) 1=features 2=segments(int32) 3=centroid_coords 4=pos_W 5=pos_b 6=max_segments
    const float* feat     = (const float*)d_in[1];
    const int*   seg      = (const int*)d_in[2];
    const float* centroid = (const float*)d_in[3];
    const float* posW     = (const float*)d_in[4];
    const float* posb     = (const float*)d_in[5];
    float* out = (float*)d_out;

    (void)in_sizes; (void)n_in; (void)out_size;

    static bool attr_set = false;
    if (!attr_set) {
        cudaFuncSetAttribute(accum_kernel,
                             cudaFuncAttributeMaxDynamicSharedMemorySize, SMEM_BYTES);
        attr_set = true;
    }

    zero_kernel<<<1024, 256>>>(out);

    dim3 grid(ROWCHUNKS, 1, BB);
    accum_kernel<<<grid, NTH, SMEM_BYTES>>>(feat, seg, out);

    int n = BB * SS * CC;
    finalize_kernel<<<(n + 255) / 256, 256>>>(out, centroid, posW, posb);
}

// round 8
// speedup vs baseline: 1.2580x; 1.2580x over previous
#include <cuda_runtime.h>
#include <cstdint>

// Problem constants (fixed-shape instance)
#define BB 16
#define CC 192
#define HH 224
#define WW 224
#define SS 196

#define ROWCHUNKS 16
#define ROWS_PER (HH / ROWCHUNKS)     // 14
#define PIX (ROWS_PER * WW)           // 3136
#define PLANE_BYTES (PIX * 4)         // 12544 (contiguous per channel per chunk)

#define NC 4                          // channels per group
#define NGROUPS (CC / NC)             // 48
#define NSTAGE 2                      // pipeline depth
#define STRIDE PIX                    // 3136 (padding irrelevant for random cross-lane conflicts)
#define GROUP_BYTES (NC * PLANE_BYTES) // 50176
#define NTH 512

// dyn smem layout (bytes):
//   ring      : NSTAGE*NC*STRIDE f32 = 100352
//   sorted_idx: PIX u16              = 6272
//   sorted_seg: PIX u8               = 3136
//   hist      : SS i32               = 784
//   mbars     : NSTAGE u64           = 16
// sort scratch (segtmp PIX i32 + scanbuf NTH i32) overlaid into ring.
#define RING_FLOATS (NSTAGE * NC * STRIDE)
#define SMEM_BYTES (RING_FLOATS * 4 + PIX * 2 + PIX + SS * 4 + 16)  // 110,560 -> 2 CTAs/SM

__device__ float g_counts[BB * SS];

__device__ __forceinline__ uint32_t smem_u32(const void* p) {
    uint32_t a;
    asm("{ .reg .u64 t; cvta.to.shared.u64 t, %1; cvt.u32.u64 %0, t; }" : "=r"(a) : "l"(p));
    return a;
}
__device__ __forceinline__ void mbar_init(uint32_t mbar, uint32_t cnt) {
    asm volatile("mbarrier.init.shared.b64 [%0], %1;" :: "r"(mbar), "r"(cnt) : "memory");
}
__device__ __forceinline__ void mbar_expect_tx(uint32_t mbar, uint32_t bytes) {
    asm volatile("mbarrier.arrive.expect_tx.shared.b64 _, [%0], %1;" :: "r"(mbar), "r"(bytes) : "memory");
}
__device__ __forceinline__ void mbar_wait(uint32_t mbar, uint32_t parity) {
    asm volatile(
        "{\n\t"
        ".reg .pred P;\n\t"
        "W_%=:\n\t"
        "mbarrier.try_wait.parity.acquire.cta.shared::cta.b64 P, [%0], %1, 0x989680;\n\t"
        "@P bra D_%=;\n\t"
        "bra W_%=;\n\t"
        "D_%=:\n\t"
        "}" :: "r"(mbar), "r"(parity) : "memory");
}
__device__ __forceinline__ void bulk_g2s(uint32_t dst, const void* src, uint32_t bytes, uint32_t mbar) {
    asm volatile("cp.async.bulk.shared::cta.global.mbarrier::complete_tx::bytes [%0], [%1], %2, [%3];"
                 :: "r"(dst), "l"(src), "r"(bytes), "r"(mbar) : "memory");
}

// ---------------- Kernel 1: zero sums (d_out) and counts ----------------
__global__ void zero_kernel(float* __restrict__ out) {
    const int n = BB * SS * CC;
    int idx = blockIdx.x * blockDim.x + threadIdx.x;
    int stride = gridDim.x * blockDim.x;
    for (int i = idx; i < n; i += stride) out[i] = 0.0f;
    for (int i = idx; i < BB * SS; i += stride) g_counts[i] = 0.0f;
}

// ---------------- Kernel 2: sort once + pipelined gather, register-cached entries ----------------
// grid: (ROWCHUNKS, 1, BB) = 256 CTAs, block: 512, 2 CTAs/SM -> single wave
__global__ __launch_bounds__(NTH, 2) void accum_kernel(
    const float* __restrict__ feat,   // (B, C, H, W) fp32
    const int* __restrict__ seg,      // (B, H, W) int32
    float* __restrict__ out)          // (B, S, C) fp32 (sums)
{
    extern __shared__ char smem_raw[];
    float* ring = (float*)smem_raw;                                   // NSTAGE*NC*STRIDE f32
    unsigned short* sorted_idx = (unsigned short*)(ring + RING_FLOATS); // PIX u16
    unsigned char*  sorted_seg = (unsigned char*)(sorted_idx + PIX);    // PIX u8
    int* hist = (int*)(sorted_seg + PIX);                             // SS
    unsigned long long* mbars = (unsigned long long*)(hist + SS);     // NSTAGE

    // sort scratch overlaid into ring (dead before TMA starts)
    int* segtmp  = (int*)ring;        // PIX ints
    int* scanbuf = segtmp + PIX;      // NTH ints

    const int tid = threadIdx.x;
    const int b   = blockIdx.z;
    const int h0  = blockIdx.x * ROWS_PER;

    const uint32_t mbar0 = smem_u32(mbars);

    if (tid == 0) {
        #pragma unroll
        for (int s = 0; s < NSTAGE; ++s) mbar_init(mbar0 + 8 * s, 1);
    }

    // ================= Phase 1: counting sort by segment id =================
    for (int i = tid; i < SS; i += NTH) hist[i] = 0;
    __syncthreads();

    const int* segbase = seg + ((size_t)b * HH + h0) * WW;   // contiguous PIX ints
    for (int i = tid; i < PIX; i += NTH) {
        int s = segbase[i];
        s = min(max(s, 0), SS - 1);
        segtmp[i] = s;
        atomicAdd(&hist[s], 1);
    }
    __syncthreads();

    // counts (each CTA owns a unique (b, rowchunk))
    for (int i = tid; i < SS; i += NTH)
        atomicAdd(&g_counts[b * SS + i], (float)hist[i]);

    // block-wide exclusive scan of hist (SS <= NTH)
    int v = (tid < SS) ? hist[tid] : 0;
    scanbuf[tid] = v;
    __syncthreads();
    #pragma unroll
    for (int d = 1; d < NTH; d <<= 1) {
        int t = (tid >= d) ? scanbuf[tid - d] : 0;
        __syncthreads();
        scanbuf[tid] += t;
        __syncthreads();
    }
    if (tid < SS) hist[tid] = scanbuf[tid] - v;  // exclusive start offsets
    __syncthreads();

    // scatter
    for (int i = tid; i < PIX; i += NTH) {
        int s = segtmp[i];
        int pos = atomicAdd(&hist[s], 1);
        sorted_idx[pos] = (unsigned short)i;
        sorted_seg[pos] = (unsigned char)s;
    }
    __syncthreads();   // sort done; ring scratch dead -> safe for TMA

    // ================= Phase 2: pipelined channel groups =================
    const float* featbase = feat + ((size_t)b * CC * HH + h0) * WW;  // + c*HH*WW
    const size_t plane = (size_t)HH * WW;
    const uint32_t ring_s = smem_u32(ring);

    // prologue: issue TMAs for groups 0..NSTAGE-1
    if (tid == 0) {
        #pragma unroll
        for (int s = 0; s < NSTAGE; ++s) {
            mbar_expect_tx(mbar0 + 8 * s, GROUP_BYTES);
            #pragma unroll
            for (int c = 0; c < NC; ++c) {
                bulk_g2s(ring_s + (uint32_t)((s * NC + c) * STRIDE) * 4,
                         featbase + (size_t)(s * NC + c) * plane,
                         PLANE_BYTES, mbar0 + 8 * s);
            }
        }
    }

    // exact 7/6 partition: threads 0..63 handle 7 entries, 64..511 handle 6
    //   64*7 + 448*6 = 3136 = PIX
    const bool has7 = (tid < 64);
    const int base  = has7 ? tid * 7 : tid * 6 + 64;

    // register-cached window: eidx[j] = pixel idx, eflush[j] = (prev_s*CC)<<1 | boundary
    int eidx[7];
    int eflush[7];
    int last_off;
    {
        int prev_s = -1;
        #pragma unroll
        for (int j = 0; j < 7; ++j) {
            int jj = base + ((j == 6 && !has7) ? 5 : j);  // replicate (unused) for 6-entry threads
            int ij = sorted_idx[jj];
            int sj = sorted_seg[jj];
            eidx[j] = ij;
            int nb = (j > 0 && sj != prev_s) ? 1 : 0;
            eflush[j] = ((prev_s < 0 ? 0 : prev_s * CC) << 1) | nb;
            prev_s = sj;
        }
        last_off = prev_s * CC;
        if (!has7) {
            // for 6-entry threads the true last segment is that of entry base+5,
            // already equal to prev_s (entry 6 replicated entry 5) -> correct.
        }
    }

    float* obase0 = out + (size_t)b * SS * CC;

    for (int g = 0; g < NGROUPS; ++g) {
        const int st = g & 1;
        const uint32_t mb = mbar0 + 8 * st;
        mbar_wait(mb, (g >> 1) & 1);

        const float* p0 = ring + (st * NC + 0) * STRIDE;
        const float* p1 = ring + (st * NC + 1) * STRIDE;
        const float* p2 = ring + (st * NC + 2) * STRIDE;
        const float* p3 = ring + (st * NC + 3) * STRIDE;
        float* obase = obase0 + g * NC;

        float a0 = 0.f, a1 = 0.f, a2 = 0.f, a3 = 0.f;

        #define STEP(j)                                                            \
        {                                                                          \
            int e  = eidx[j];                                                      \
            float v0 = p0[e], v1 = p1[e], v2 = p2[e], v3 = p3[e];                  \
            int fo = eflush[j];                                                    \
            float* oaddr = obase + (fo >> 1);                                      \
            asm volatile(                                                          \
                "{ .reg .pred p; setp.ne.s32 p, %0, 0;\n\t"                        \
                "@p red.global.add.v4.f32 [%1], {%2,%3,%4,%5}; }"                  \
                :: "r"(fo & 1), "l"(oaddr),                                        \
                   "f"(a0), "f"(a1), "f"(a2), "f"(a3) : "memory");                 \
            bool nb = (fo & 1);                                                    \
            a0 = nb ? v0 : a0 + v0;                                                \
            a1 = nb ? v1 : a1 + v1;                                                \
            a2 = nb ? v2 : a2 + v2;                                                \
            a3 = nb ? v3 : a3 + v3;                                                \
        }

        STEP(0) STEP(1) STEP(2) STEP(3) STEP(4) STEP(5)
        if (has7) { STEP(6) }   // warp-uniform (warps 0,1 only)
        #undef STEP

        // final flush (every thread has >= 1 entry)
        asm volatile("red.global.add.v4.f32 [%0], {%1,%2,%3,%4};"
                     :: "l"(obase + last_off), "f"(a0), "f"(a1), "f"(a2), "f"(a3)
                     : "memory");

        __syncthreads();   // all gathers on buffer st complete before refill

        if (tid == 0 && g + NSTAGE < NGROUPS) {
            const int gn = g + NSTAGE;
            mbar_expect_tx(mb, GROUP_BYTES);
            #pragma unroll
            for (int c = 0; c < NC; ++c) {
                bulk_g2s(ring_s + (uint32_t)((st * NC + c) * STRIDE) * 4,
                         featbase + (size_t)(gn * NC + c) * plane,
                         PLANE_BYTES, mb);
            }
        }
    }
}

// ---------------- Kernel 3: finalize (divide by count, add positional embedding) ----------------
__global__ void finalize_kernel(
    float* __restrict__ out,                   // (B, S, C) sums -> final
    const float* __restrict__ centroid,        // (B, S, 2)
    const float* __restrict__ posW,            // (2, C)
    const float* __restrict__ posb)            // (C,)
{
    int idx = blockIdx.x * blockDim.x + threadIdx.x;
    if (idx >= BB * SS * CC) return;
    int c  = idx % CC;
    int bs = idx / CC;
    float cnt = g_counts[bs];
    float cx = centroid[bs * 2 + 0] * (1.0f / WW);
    float cy = centroid[bs * 2 + 1] * (1.0f / HH);
    float pos = fmaf(cx, posW[c], fmaf(cy, posW[CC + c], posb[c]));
    out[idx] = out[idx] / fmaxf(cnt, 1.0f) + pos;
}

extern "C" void kernel_launch(void* const* d_in, const int* in_sizes, int n_in,
                              void* d_out, int out_size)
{
    // inputs: 0=img(unused) 1=features 2=segments(int32) 3=centroid_coords 4=pos_W 5=pos_b 6=max_segments
    const float* feat     = (const float*)d_in[1];
    const int*   seg      = (const int*)d_in[2];
    const float* centroid = (const float*)d_in[3];
    const float* posW     = (const float*)d_in[4];
    const float* posb     = (const float*)d_in[5];
    float* out = (float*)d_out;

    (void)in_sizes; (void)n_in; (void)out_size;

    static bool attr_set = false;
    if (!attr_set) {
        cudaFuncSetAttribute(accum_kernel,
                             cudaFuncAttributeMaxDynamicSharedMemorySize, SMEM_BYTES);
        attr_set = true;
    }

    zero_kernel<<<1024, 256>>>(out);

    dim3 grid(ROWCHUNKS, 1, BB);
    accum_kernel<<<grid, NTH, SMEM_BYTES>>>(feat, seg, out);

    int n = BB * SS * CC;
    finalize_kernel<<<(n + 255) / 256, 256>>>(out, centroid, posW, posb);
}